// round 6
// baseline (speedup 1.0000x reference)
#include <cuda_runtime.h>
#include <math.h>

#define BATCH 256
#define NCHK  512
#define NVAR  1024
#define DVd   3
#define DD    16
#define EE    3072

#define C_IN   97
#define C_HID  388
#define C_OUT  96
#define V_IN   49
#define V_HID  196
#define V_OUT  49

// Persistent message buffers
__device__ float g_Mc[(size_t)BATCH*EE*DD];   // 50.3 MB
__device__ float g_Mv[(size_t)BATCH*EE*DD];   // 50.3 MB

// Fragment-ordered tf32 weight buffers (filled once per launch)
__device__ unsigned g_cW1f[7*7*12*64];        // [cc][nt][kt][lane][2]
__device__ unsigned g_cW2f[7*12*7*64];        // [cc][nt][ktl][lane][2]
__device__ unsigned g_vW1f[4*7*6*64];         // [cc][nt][kt][lane][2]
__device__ unsigned g_vW2f[4*7*7*64];         // [cc][nt][ktl][lane][2]

__device__ __forceinline__ float rcp_fast(float x){
    float r; asm("rcp.approx.f32 %0, %1;" : "=f"(r) : "f"(x)); return r;
}
// Branchless gelu: 0.5x(1+erf(x/sqrt2)), A&S 7.1.26 erf (max abs err 1.5e-7)
__device__ __forceinline__ float gelu_fast(float x){
    float z = fabsf(x) * 0.7071067811865476f;
    float t = rcp_fast(fmaf(0.3275911f, z, 1.0f));
    float p = fmaf(t, 1.061405429f, -1.453152027f);
    p = fmaf(t, p, 1.421413741f);
    p = fmaf(t, p, -0.284496736f);
    p = fmaf(t, p, 0.254829592f);
    p *= t;
    float e = __expf(-0.5f * x * x);
    float erfa = fmaf(-p, e, 1.0f);
    float s = copysignf(erfa, x);
    return 0.5f * x * (1.0f + s);
}
__device__ __forceinline__ unsigned f2tf32(float x){
    unsigned r; asm("cvt.rn.tf32.f32 %0, %1;" : "=r"(r) : "f"(x)); return r;
}
__device__ __forceinline__ void mma_tf32(float* d, const unsigned* a, unsigned b0, unsigned b1){
    asm volatile("mma.sync.aligned.m16n8k8.row.col.f32.tf32.tf32.f32 "
        "{%0,%1,%2,%3},{%4,%5,%6,%7},{%8,%9},{%0,%1,%2,%3};"
        : "+f"(d[0]),"+f"(d[1]),"+f"(d[2]),"+f"(d[3])
        : "r"(a[0]),"r"(a[1]),"r"(a[2]),"r"(a[3]), "r"(b0),"r"(b1));
}

// ---------------------------------------------------------------------------
__global__ void init_kernel(const float* __restrict__ prior,
                            const int* __restrict__ perm)
{
    int idx = blockIdx.x * blockDim.x + threadIdx.x;
    if (idx >= BATCH*EE*DD) return;
    int d  = idx & (DD-1);
    int bp = idx >> 4;
    int p  = bp % EE;
    int b  = bp / EE;
    int j  = perm[p];
    float v = (d == 0) ? prior[p / DVd] : 0.0f;
    g_Mc[((size_t)b*EE + j)*DD + d] = v;
}

// ---------------------------------------------------------------------------
__global__ void prep_check(const float* __restrict__ W1, const float* __restrict__ W2)
{
    int idx = blockIdx.x*blockDim.x + threadIdx.x;
    if (idx < 37632) {
        int s = idx & 1, l = (idx >> 1) & 31;
        int r = idx >> 6;
        int kt = r % 12; r /= 12;
        int nt = r % 7;  int cc = r / 7;
        int gid = l >> 2, tig = l & 3;
        int k = kt*8 + tig + 4*s;                 // < 96
        int n = cc*56 + nt*8 + gid;
        float v = (n < C_HID) ? W1[k*C_HID + n] : 0.0f;
        g_cW1f[idx] = f2tf32(v);
    } else if (idx < 75264) {
        int j = idx - 37632;
        int s = j & 1, l = (j >> 1) & 31;
        int r = j >> 6;
        int ktl = r % 7; r /= 7;
        int nt = r % 12; int cc = r / 12;
        int gid = l >> 2, tig = l & 3;
        int k = cc*56 + ktl*8 + tig + 4*s;
        int n = nt*8 + gid;                       // < 96
        float v = (k < C_HID) ? W2[k*C_OUT + n] : 0.0f;
        g_cW2f[j] = f2tf32(v);
    }
}

__global__ void prep_var(const float* __restrict__ W1, const float* __restrict__ W2)
{
    int idx = blockIdx.x*blockDim.x + threadIdx.x;
    if (idx < 10752) {
        int s = idx & 1, l = (idx >> 1) & 31;
        int r = idx >> 6;
        int kt = r % 6; r /= 6;
        int nt = r % 7; int cc = r / 7;
        int gid = l >> 2, tig = l & 3;
        int k = kt*8 + tig + 4*s;                 // < 48
        int n = cc*56 + nt*8 + gid;
        float v = (n < V_HID) ? W1[k*V_HID + n] : 0.0f;
        g_vW1f[idx] = f2tf32(v);
    } else if (idx < 23296) {
        int j = idx - 10752;
        int s = j & 1, l = (j >> 1) & 31;
        int r = j >> 6;
        int ktl = r % 7; r /= 7;
        int nt = r % 7; int cc = r / 7;
        int gid = l >> 2, tig = l & 3;
        int k = cc*56 + ktl*8 + tig + 4*s;
        int n = nt*8 + gid;
        float v = (k < V_HID && n < V_OUT) ? W2[k*V_OUT + n] : 0.0f;
        g_vW2f[j] = f2tf32(v);
    }
}

// ---------------------------------------------------------------------------
// CHECK: 131072 rows. 128 thr (4 warps), m32/warp (2 m16 tiles), 128 rows/CTA.
// Each B fragment (__ldg) feeds 2 MMAs -> L1 B-traffic halved.
// ---------------------------------------------------------------------------
#define UHS 61

__global__ __launch_bounds__(128, 2)
void check_kernel(const int* __restrict__ synd,
                  const float* __restrict__ W1raw, const float* __restrict__ B1,
                  const float* __restrict__ B2)
{
    extern __shared__ unsigned smem[];
    uint4*    sXf  = (uint4*)smem;                 // 4w*2t*12kt*32 = 3072 uint4
    unsigned* sH   = smem + 12288;                 // 4*32*61 = 7808 words
    float*    sb1a = (float*)(sH + 4*32*UHS);      // 392
    float*    sw1r = sb1a + 392;                   // 392
    float*    sb2  = sw1r + 392;                   // 96

    const int tid  = threadIdx.x;
    const int warp = tid >> 5, lane = tid & 31;
    const int gid  = lane >> 2, tig = lane & 3;
    const int base_row = blockIdx.x * 128;
    const int r0 = base_row + warp*32 + gid;       // rows r0, +8, +16, +24

    // ---- prologue ----
    for (int i = tid; i < 392; i += 128) {
        bool ok = i < C_HID;
        sb1a[i] = ok ? B1[i] : 0.0f;
        sw1r[i] = ok ? W1raw[96*C_HID + i] : 0.0f;
    }
    if (tid < 96) sb2[tid] = B2[tid];

    uint4* myX0 = sXf + (warp*2 + 0)*12*32 + lane;
    uint4* myX1 = sXf + (warp*2 + 1)*12*32 + lane;
    {
        #pragma unroll
        for (int t = 0; t < 2; t++) {
            const float* xlo = g_Mc + (size_t)(r0 + t*16) * 96;
            const float* xhi = g_Mc + (size_t)(r0 + t*16 + 8) * 96;
            uint4* dst = t ? myX1 : myX0;
            #pragma unroll
            for (int kt = 0; kt < 12; kt++) {
                int c = kt*8 + tig;
                uint4 v;
                v.x = f2tf32(xlo[c]);   v.y = f2tf32(xhi[c]);
                v.z = f2tf32(xlo[c+4]); v.w = f2tf32(xhi[c+4]);
                dst[kt*32] = v;
            }
        }
    }
    float sg[4];
    #pragma unroll
    for (int q = 0; q < 4; q++)
        sg[q] = 1.0f - 2.0f * (float)synd[r0 + q*8];
    __syncthreads();

    float acc2[2][12][4];
    #pragma unroll
    for (int t = 0; t < 2; t++)
        #pragma unroll
        for (int n = 0; n < 12; n++)
            #pragma unroll
            for (int i = 0; i < 4; i++) acc2[t][n][i] = 0.0f;

    unsigned* sHw = sH + warp*32*UHS;

    for (int cc = 0; cc < 7; cc++) {
        // ---- layer 1 (m32 x n56, K=96) ----
        float acc1[2][7][4];
        #pragma unroll
        for (int nt = 0; nt < 7; nt++) {
            #pragma unroll
            for (int i = 0; i < 4; i++) {
                float w = sw1r[cc*56 + nt*8 + 2*tig + (i & 1)];
                acc1[0][nt][i] = sg[i >> 1]       * w;
                acc1[1][nt][i] = sg[2 + (i >> 1)] * w;
            }
        }
        const uint2* wp1 = (const uint2*)g_cW1f + (size_t)cc*7*12*32 + lane;
        #pragma unroll 4
        for (int kt = 0; kt < 12; kt++) {
            uint4 a04 = myX0[kt*32];
            uint4 a14 = myX1[kt*32];
            unsigned a0[4] = {a04.x, a04.y, a04.z, a04.w};
            unsigned a1[4] = {a14.x, a14.y, a14.z, a14.w};
            #pragma unroll
            for (int nt = 0; nt < 7; nt++) {
                uint2 b = __ldg(wp1 + (size_t)(nt*12 + kt)*32);
                mma_tf32(acc1[0][nt], a0, b.x, b.y);
                mma_tf32(acc1[1][nt], a1, b.x, b.y);
            }
        }

        // ---- gelu -> warp H (tf32), 32 rows ----
        #pragma unroll
        for (int nt = 0; nt < 7; nt++) {
            #pragma unroll
            for (int t = 0; t < 2; t++) {
                #pragma unroll
                for (int i = 0; i < 4; i++) {
                    int rowloc = t*16 + gid + ((i >> 1) << 3);
                    int colloc = nt*8 + 2*tig + (i & 1);
                    float h = gelu_fast(acc1[t][nt][i] + sb1a[cc*56 + colloc]);
                    sHw[rowloc*UHS + colloc] = f2tf32(h);
                }
            }
        }
        __syncwarp();

        // ---- layer 2 partial (m32 x n96, K=56) ----
        const uint2* wp2 = (const uint2*)g_cW2f + (size_t)cc*12*7*32 + lane;
        #pragma unroll 2
        for (int ktl = 0; ktl < 7; ktl++) {
            unsigned a0[4], a1[4];
            a0[0] = sHw[gid*UHS        + ktl*8 + tig];
            a0[1] = sHw[(gid+8)*UHS    + ktl*8 + tig];
            a0[2] = sHw[gid*UHS        + ktl*8 + tig + 4];
            a0[3] = sHw[(gid+8)*UHS    + ktl*8 + tig + 4];
            a1[0] = sHw[(gid+16)*UHS   + ktl*8 + tig];
            a1[1] = sHw[(gid+24)*UHS   + ktl*8 + tig];
            a1[2] = sHw[(gid+16)*UHS   + ktl*8 + tig + 4];
            a1[3] = sHw[(gid+24)*UHS   + ktl*8 + tig + 4];
            #pragma unroll
            for (int nt = 0; nt < 12; nt++) {
                uint2 b = __ldg(wp2 + (size_t)(nt*7 + ktl)*32);
                mma_tf32(acc2[0][nt], a0, b.x, b.y);
                mma_tf32(acc2[1][nt], a1, b.x, b.y);
            }
        }
        __syncwarp();
    }

    // ---- epilogue ----
    #pragma unroll
    for (int nt = 0; nt < 12; nt++) {
        int col = nt*8 + 2*tig;
        float bb0 = sb2[col], bb1 = sb2[col+1];
        #pragma unroll
        for (int t = 0; t < 2; t++) {
            #pragma unroll
            for (int half = 0; half < 2; half++) {
                int row = r0 + t*16 + half*8;
                float sgv = sg[t*2 + half];
                float2 y;
                y.x = (acc2[t][nt][half*2+0] + bb0) * sgv;
                y.y = (acc2[t][nt][half*2+1] + bb1) * sgv;
                *(float2*)(g_Mv + (size_t)row*96 + col) = y;
            }
        }
    }
}

// ---------------------------------------------------------------------------
// VAR: 262144 rows. 128 thr (4 warps), m32/warp, 128 rows/CTA, 3 CTAs/SM.
// ---------------------------------------------------------------------------
__global__ __launch_bounds__(128, 3)
void var_kernel(const int* __restrict__ perm,
                const float* __restrict__ prior,
                const float* __restrict__ W1raw, const float* __restrict__ B1,
                const float* __restrict__ B2,
                float* __restrict__ out_llr)
{
    extern __shared__ unsigned smem[];
    uint4*    sXf  = (uint4*)smem;                 // 4w*2t*6kt*32 = 1536 uint4
    unsigned* sH   = smem + 6144;                  // 7808 words
    float*    sb1a = (float*)(sH + 4*32*UHS);      // 224
    float*    sw1r = sb1a + 224;                   // 224
    float*    sb2  = sw1r + 224;                   // 49

    const int tid  = threadIdx.x;
    const int warp = tid >> 5, lane = tid & 31;
    const int gid  = lane >> 2, tig = lane & 3;
    const int base_row = blockIdx.x * 128;
    const int r0 = base_row + warp*32 + gid;       // rows r0,+8,+16,+24

    for (int i = tid; i < 224; i += 128) {
        bool ok = i < V_HID;
        sb1a[i] = ok ? B1[i] : 0.0f;
        sw1r[i] = ok ? W1raw[48*V_HID + i] : 0.0f;
    }
    if (tid < 49) sb2[tid] = B2[tid];

    int rw[4], bb[4], vv[4], pp[4][3];
    float pr[4];
    #pragma unroll
    for (int q = 0; q < 4; q++) {
        rw[q] = r0 + q*8;
        bb[q] = rw[q] >> 10;
        vv[q] = rw[q] & 1023;
        pr[q] = prior[vv[q]];
        #pragma unroll
        for (int e = 0; e < 3; e++) pp[q][e] = perm[vv[q]*DVd + e];
    }

    uint4* myX0 = sXf + (warp*2 + 0)*6*32 + lane;
    uint4* myX1 = sXf + (warp*2 + 1)*6*32 + lane;
    {
        #pragma unroll
        for (int t = 0; t < 2; t++) {
            const float* blo = g_Mv + (size_t)bb[t*2]  *EE*DD;
            const float* bhi = g_Mv + (size_t)bb[t*2+1]*EE*DD;
            uint4* dst = t ? myX1 : myX0;
            #pragma unroll
            for (int kt = 0; kt < 6; kt++) {
                int e = kt >> 1;
                int d = ((kt & 1) << 3) + tig;
                uint4 v;
                v.x = f2tf32(blo[pp[t*2][e]*DD + d]);
                v.y = f2tf32(bhi[pp[t*2+1][e]*DD + d]);
                v.z = f2tf32(blo[pp[t*2][e]*DD + d + 4]);
                v.w = f2tf32(bhi[pp[t*2+1][e]*DD + d + 4]);
                dst[kt*32] = v;
            }
        }
    }
    __syncthreads();

    float acc2[2][7][4];
    #pragma unroll
    for (int t = 0; t < 2; t++)
        #pragma unroll
        for (int n = 0; n < 7; n++)
            #pragma unroll
            for (int i = 0; i < 4; i++) acc2[t][n][i] = 0.0f;

    unsigned* sHw = sH + warp*32*UHS;

    for (int cc = 0; cc < 4; cc++) {
        float acc1[2][7][4];
        #pragma unroll
        for (int nt = 0; nt < 7; nt++) {
            #pragma unroll
            for (int i = 0; i < 4; i++) {
                float w = sw1r[cc*56 + nt*8 + 2*tig + (i & 1)];
                acc1[0][nt][i] = pr[i >> 1]       * w;
                acc1[1][nt][i] = pr[2 + (i >> 1)] * w;
            }
        }
        const uint2* wp1 = (const uint2*)g_vW1f + (size_t)cc*7*6*32 + lane;
        #pragma unroll 3
        for (int kt = 0; kt < 6; kt++) {
            uint4 a04 = myX0[kt*32];
            uint4 a14 = myX1[kt*32];
            unsigned a0[4] = {a04.x, a04.y, a04.z, a04.w};
            unsigned a1[4] = {a14.x, a14.y, a14.z, a14.w};
            #pragma unroll
            for (int nt = 0; nt < 7; nt++) {
                uint2 b = __ldg(wp1 + (size_t)(nt*6 + kt)*32);
                mma_tf32(acc1[0][nt], a0, b.x, b.y);
                mma_tf32(acc1[1][nt], a1, b.x, b.y);
            }
        }

        #pragma unroll
        for (int nt = 0; nt < 7; nt++) {
            #pragma unroll
            for (int t = 0; t < 2; t++) {
                #pragma unroll
                for (int i = 0; i < 4; i++) {
                    int rowloc = t*16 + gid + ((i >> 1) << 3);
                    int colloc = nt*8 + 2*tig + (i & 1);
                    float h = gelu_fast(acc1[t][nt][i] + sb1a[cc*56 + colloc]);
                    sHw[rowloc*UHS + colloc] = f2tf32(h);
                }
            }
        }
        __syncwarp();

        const uint2* wp2 = (const uint2*)g_vW2f + (size_t)cc*7*7*32 + lane;
        #pragma unroll 2
        for (int ktl = 0; ktl < 7; ktl++) {
            unsigned a0[4], a1[4];
            a0[0] = sHw[gid*UHS        + ktl*8 + tig];
            a0[1] = sHw[(gid+8)*UHS    + ktl*8 + tig];
            a0[2] = sHw[gid*UHS        + ktl*8 + tig + 4];
            a0[3] = sHw[(gid+8)*UHS    + ktl*8 + tig + 4];
            a1[0] = sHw[(gid+16)*UHS   + ktl*8 + tig];
            a1[1] = sHw[(gid+24)*UHS   + ktl*8 + tig];
            a1[2] = sHw[(gid+16)*UHS   + ktl*8 + tig + 4];
            a1[3] = sHw[(gid+24)*UHS   + ktl*8 + tig + 4];
            #pragma unroll
            for (int nt = 0; nt < 7; nt++) {
                uint2 b = __ldg(wp2 + (size_t)(nt*7 + ktl)*32);
                mma_tf32(acc2[0][nt], a0, b.x, b.y);
                mma_tf32(acc2[1][nt], a1, b.x, b.y);
            }
        }
        __syncwarp();
    }

    // ---- epilogue: scatter via perm regs ----
    #pragma unroll
    for (int nt = 0; nt < 7; nt++) {
        #pragma unroll
        for (int t = 0; t < 2; t++) {
            #pragma unroll
            for (int i = 0; i < 4; i++) {
                int col = nt*8 + 2*tig + (i & 1);
                if (col > 48) continue;
                int q = t*2 + (i >> 1);
                float y = acc2[t][nt][i] + sb2[col];
                if (col < 48) {
                    int e = col >> 4, d = col & 15;
                    g_Mc[((size_t)bb[q]*EE + pp[q][e])*DD + d] = y;
                } else {
                    out_llr[rw[q]] = y;
                }
            }
        }
    }
}

// ---------------------------------------------------------------------------
extern "C" void kernel_launch(void* const* d_in, const int* in_sizes, int n_in,
                              void* d_out, int out_size)
{
    const int*   synd  = (const int*)  d_in[0];
    const float* prior = (const float*)d_in[2];
    const int*   perm  = (const int*)  d_in[3];
    const float* cW1   = (const float*)d_in[4];
    const float* cb1   = (const float*)d_in[5];
    const float* cW2   = (const float*)d_in[6];
    const float* cb2   = (const float*)d_in[7];
    const float* vW1   = (const float*)d_in[8];
    const float* vb1   = (const float*)d_in[9];
    const float* vW2   = (const float*)d_in[10];
    const float* vb2   = (const float*)d_in[11];
    float* out = (float*)d_out;

    const int T = out_size / (BATCH * NVAR);

    const int check_smem = (12288 + 4*32*UHS)*4 + (392+392+96)*4 + 64;   // ~84 KB
    const int var_smem   = (6144  + 4*32*UHS)*4 + (224+224+49)*4 + 64;   // ~58 KB

    cudaFuncSetAttribute(check_kernel, cudaFuncAttributeMaxDynamicSharedMemorySize, check_smem);
    cudaFuncSetAttribute(var_kernel,   cudaFuncAttributeMaxDynamicSharedMemorySize, var_smem);

    init_kernel<<<(BATCH*EE*DD + 255)/256, 256>>>(prior, perm);
    prep_check<<<(75264 + 255)/256, 256>>>(cW1, cW2);
    prep_var<<<(23296 + 255)/256, 256>>>(vW1, vW2);

    const int check_blocks = (BATCH*NCHK) / 128;   // 1024
    const int var_blocks   = (BATCH*NVAR) / 128;   // 2048

    for (int t = 0; t < T; t++) {
        check_kernel<<<check_blocks, 128, check_smem>>>(synd, cW1, cb1, cb2);
        var_kernel<<<var_blocks, 128, var_smem>>>(perm, prior, vW1, vb1, vb2,
                                                  out + (size_t)t * BATCH * NVAR);
    }
}